// round 17
// baseline (speedup 1.0000x reference)
#include <cuda_runtime.h>
#include <cmath>
#include <cstdint>

#define N_LEVELS 16
#define TBL_STRIDE 524288u   // 2^19 entries per level
#define OUT_COMPS 35         // 3 (x passthrough) + 16*2 feats
#define THREADS 256
#define HASH_MASK 524287u    // 2^19 - 1; levels >= 6 are always fully hashed

struct Params {
    float res[N_LEVELS];
    unsigned hms[N_LEVELS];
    unsigned long long magic[N_LEVELS];
};

// Lemire fastmod: n % d with M = 2^64/d + 1 (exact for all n < 2^32)
__device__ __forceinline__ unsigned fastmod(unsigned n, unsigned d, unsigned long long M) {
    unsigned long long low = M * (unsigned long long)n;
    return (unsigned)__umul64hi(low, (unsigned long long)d);
}

// Per-level geometry.
struct LevelGeom {
    unsigned a0, hb0, hb1, hc0, hc1;
    float fx, fy, fz;
};

__device__ __forceinline__ LevelGeom make_geom(float x0, float x1, float x2, float r) {
    const unsigned P1 = 2654435761u;
    const unsigned P2 = 805459861u;
    LevelGeom g;
    const float xs0 = x0 * r, xs1 = x1 * r, xs2 = x2 * r;
    const float fl0 = floorf(xs0), fl1 = floorf(xs1), fl2 = floorf(xs2);
    g.fx = xs0 - fl0; g.fy = xs1 - fl1; g.fz = xs2 - fl2;
    g.a0  = (unsigned)(int)fl0;
    g.hb0 = (unsigned)(int)fl1 * P1;  g.hb1 = g.hb0 + P1;
    g.hc0 = (unsigned)(int)fl2 * P2;  g.hc1 = g.hc0 + P2;
    return g;
}

// Fully-hashed level (d = 2^19, mask-mod).
__device__ __forceinline__ void load_hashed(const LevelGeom& g,
                                            const float2* __restrict__ tb,
                                            float2 e[8]) {
    const unsigned hb[2] = {g.hb0, g.hb1};
    const unsigned hc[2] = {g.hc0, g.hc1};
    if ((g.a0 & 1u) == 0u) {
#pragma unroll
        for (int pr = 0; pr < 4; pr++) {
            const int iy = pr & 1, iz = pr >> 1;
            const unsigned m0 = (g.a0 ^ hb[iy] ^ hc[iz]) & HASH_MASK;
            const float4 q = __ldcg((const float4*)tb + (m0 >> 1));
            const float2 lo = make_float2(q.x, q.y);
            const float2 hi = make_float2(q.z, q.w);
            const bool odd = (m0 & 1u) != 0u;
            const int n = (iy << 1) | (iz << 2);
            e[n]     = odd ? hi : lo;
            e[n | 1] = odd ? lo : hi;
        }
    } else {
#pragma unroll
        for (int pr = 0; pr < 4; pr++) {
            const int iy = pr & 1, iz = pr >> 1;
            const unsigned hbc = hb[iy] ^ hc[iz];
            const int n = (iy << 1) | (iz << 2);
            e[n]     = __ldcg(tb + ((g.a0 ^ hbc) & HASH_MASK));
            e[n | 1] = __ldcg(tb + (((g.a0 + 1u) ^ hbc) & HASH_MASK));
        }
    }
}

// Mod level. EVEN_D: even hms => a0-even guarantees aligned pair (parity
// preserved by even-d mod). Otherwise runtime merge check. L1: allocate in L1.
template <bool EVEN_D, bool L1>
__device__ __forceinline__ void load_mod(const LevelGeom& g,
                                         const float2* __restrict__ tb,
                                         unsigned d, unsigned long long M,
                                         float2 e[8]) {
    const unsigned hb[2] = {g.hb0, g.hb1};
    const unsigned hc[2] = {g.hc0, g.hc1};
    if (EVEN_D && (g.a0 & 1u) == 0u) {
#pragma unroll
        for (int pr = 0; pr < 4; pr++) {
            const int iy = pr & 1, iz = pr >> 1;
            const unsigned m0 = fastmod(g.a0 ^ hb[iy] ^ hc[iz], d, M);
            const float4 q = L1 ? __ldg((const float4*)tb + (m0 >> 1))
                                : __ldcg((const float4*)tb + (m0 >> 1));
            const float2 lo = make_float2(q.x, q.y);
            const float2 hi = make_float2(q.z, q.w);
            const bool odd = (m0 & 1u) != 0u;
            const int n = (iy << 1) | (iz << 2);
            e[n]     = odd ? hi : lo;
            e[n | 1] = odd ? lo : hi;
        }
    } else if (EVEN_D) {
#pragma unroll
        for (int pr = 0; pr < 4; pr++) {
            const int iy = pr & 1, iz = pr >> 1;
            const unsigned hbc = hb[iy] ^ hc[iz];
            const unsigned m0 = fastmod(g.a0 ^ hbc, d, M);
            const unsigned m1 = fastmod((g.a0 + 1u) ^ hbc, d, M);
            const int n = (iy << 1) | (iz << 2);
            e[n]     = L1 ? __ldg(tb + m0) : __ldcg(tb + m0);
            e[n | 1] = L1 ? __ldg(tb + m1) : __ldcg(tb + m1);
        }
    } else {
#pragma unroll
        for (int pr = 0; pr < 4; pr++) {
            const int iy = pr & 1, iz = pr >> 1;
            const unsigned hbc = hb[iy] ^ hc[iz];
            const unsigned m0 = fastmod(g.a0 ^ hbc, d, M);
            const unsigned m1 = fastmod((g.a0 + 1u) ^ hbc, d, M);
            const int n = (iy << 1) | (iz << 2);
            if ((m0 ^ m1) == 1u) {
                const float4 q = __ldcg((const float4*)tb + (m0 >> 1));
                const float2 lo = make_float2(q.x, q.y);
                const float2 hi = make_float2(q.z, q.w);
                const bool odd = (m0 & 1u) != 0u;
                e[n]     = odd ? hi : lo;
                e[n | 1] = odd ? lo : hi;
            } else {
                e[n]     = __ldcg(tb + m0);
                e[n | 1] = __ldcg(tb + m1);
            }
        }
    }
}

// Compile-time-folded per-level dispatch (l is constant inside #pragma unroll).
// hms: l0=4096(e) l1=10648(e) l2=27000(e) l3=68921(o) l4=185193(o) l5=512000(e)
__device__ __forceinline__ void load_any(int l, const LevelGeom& g,
                                         const float2* __restrict__ tbase,
                                         const Params& prm, float2 e[8]) {
    const float2* __restrict__ tb = tbase + (size_t)l * TBL_STRIDE;
    if (l >= 6) {
        load_hashed(g, tb, e);
    } else if (l == 3 || l == 4) {
        load_mod<false, false>(g, tb, prm.hms[l], prm.magic[l], e);
    } else if (l < 3) {
        load_mod<true, true>(g, tb, prm.hms[l], prm.magic[l], e);
    } else {  // l == 5
        load_mod<true, false>(g, tb, prm.hms[l], prm.magic[l], e);
    }
}

__device__ __forceinline__ void consume(const LevelGeom& g, const float2 e[8],
                                        float* dst) {
    const float wx[2] = {1.0f - g.fx, g.fx};
    const float wy[2] = {1.0f - g.fy, g.fy};
    const float wz[2] = {1.0f - g.fz, g.fz};
    // Reference computes prod left-to-right: (wx*wy)*wz. Factor the shared
    // (wx*wy) products (4 distinct, each used for 2 z-corners): 4+8 = 12 muls
    // instead of 16, identical association order -> bit-identical results.
    float wxy[4];
#pragma unroll
    for (int p = 0; p < 4; p++)
        wxy[p] = wx[p & 1] * wy[p >> 1];
    float acc0 = 0.0f, acc1 = 0.0f;
#pragma unroll
    for (int n = 0; n < 8; n++) {
        const float w = wxy[n & 3] * wz[n >> 2];
        acc0 = fmaf(e[n].x, w, acc0);
        acc1 = fmaf(e[n].y, w, acc1);
    }
    dst[0] = acc0;
    dst[1] = acc1;
}

__global__ __launch_bounds__(THREADS, 3)
void hashgrid_kernel(const float* __restrict__ x,
                     const float2* __restrict__ tables,
                     float* __restrict__ out,
                     Params prm) {
    __shared__ float stage[THREADS * OUT_COMPS];

    const int pt = blockIdx.x * THREADS + threadIdx.x;

    const float x0 = x[pt * 3 + 0];
    const float x1 = x[pt * 3 + 1];
    const float x2 = x[pt * 3 + 2];

    float* my = &stage[threadIdx.x * OUT_COMPS];
    my[0] = x0; my[1] = x1; my[2] = x2;

    const float2* __restrict__ tbase = tables;

    // ── All 16 levels: depth-3 software-pipelined sliding window.
    // Prologue loads levels 0,1,2; steady state consumes level l-3 and issues
    // level l's loads into the freed slot; epilogue consumes 13,14,15.
    // 2-3 levels' gathers stay in flight at all times — no drain bubbles at
    // level boundaries, including the mod->hashed transition.
    {
        LevelGeom g[3];
        float2 e[3][8];

#pragma unroll
        for (int i = 0; i < 3; i++) {
            g[i] = make_geom(x0, x1, x2, prm.res[i]);
            load_any(i, g[i], tbase, prm, e[i]);
        }

#pragma unroll
        for (int l = 3; l < 16; l++) {
            const int slot = l % 3;              // slot holding level l-3
            consume(g[slot], e[slot], &my[3 + 2 * (l - 3)]);
            g[slot] = make_geom(x0, x1, x2, prm.res[l]);
            load_any(l, g[slot], tbase, prm, e[slot]);
        }

#pragma unroll
        for (int l = 13; l < 16; l++) {
            const int slot = l % 3;
            consume(g[slot], e[slot], &my[3 + 2 * l]);
        }
    }

    __syncwarp();

    // Coalesced writeout: each warp copies its 32 rows (32*35 floats = 4480 B,
    // 16B-aligned in smem and gmem) as float4 streaming stores.
    const int lane = threadIdx.x & 31;
    const int warp_first = (blockIdx.x * THREADS) + (threadIdx.x & ~31);
    const float4* src = (const float4*)&stage[(threadIdx.x & ~31) * OUT_COMPS];
    float4* dst = (float4*)(out + (size_t)warp_first * OUT_COMPS);
#pragma unroll
    for (int j = lane; j < (32 * OUT_COMPS) / 4; j += 32) {
        __stcs(&dst[j], src[j]);
    }
}

extern "C" void kernel_launch(void* const* d_in, const int* in_sizes, int n_in,
                              void* d_out, int out_size) {
    const float*  x      = (const float*)d_in[0];
    const float2* tables = (const float2*)d_in[1];
    float*        out    = (float*)d_out;

    // Level params via the exact same double-precision libm sequence as the
    // Python reference (same machine/libm => bit-identical results).
    Params prm;
    const double beta = exp((log(2048.0) - log(16.0)) / 15.0);
    for (int l = 0; l < N_LEVELS; l++) {
        const double r = floor(16.0 * pow(beta, (double)l));
        prm.res[l] = (float)r;
        const long long ri = (long long)r;
        long long h3 = ri * ri * ri;
        if (h3 > 524288LL) h3 = 524288LL;
        const unsigned d = (unsigned)h3;
        prm.hms[l] = d;
        prm.magic[l] = 0xFFFFFFFFFFFFFFFFull / d + 1ull;
    }

    const int npts = in_sizes[0] / 3;
    const int blocks = (npts + THREADS - 1) / THREADS;
    hashgrid_kernel<<<blocks, THREADS>>>(x, tables, out, prm);
}